// round 14
// baseline (speedup 1.0000x reference)
#include <cuda_runtime.h>
#include <cuda_bf16.h>
#include <cuda_fp16.h>
#include <math.h>

#define MAXN 50000
#define MAXE 800000
#define INC 128

typedef unsigned long long u64;
typedef unsigned int u32;

// ---------------- scratch (no allocation allowed) ----------------
__device__ __align__(16) float g_bufA[MAXN * 128];
__device__ __align__(16) float g_bufB[MAXN * 128];
__device__ float g_dinv[MAXN];
__device__ int   g_deg[MAXN];
__device__ int   g_off[MAXN + 1];
__device__ int   g_col[MAXE];
__device__ int   g_pref[64];

// ---------------- helpers ----------------
__device__ __forceinline__ float4 h4f(u64 v) {
    __half2 a = reinterpret_cast<__half2*>(&v)[0];
    __half2 b = reinterpret_cast<__half2*>(&v)[1];
    float2 fa = __half22float2(a), fb = __half22float2(b);
    return make_float4(fa.x, fa.y, fb.x, fb.y);
}
__device__ __forceinline__ u64 f4h(float4 v) {
    u64 r;
    reinterpret_cast<__half2*>(&r)[0] = __floats2half2_rn(v.x, v.y);
    reinterpret_cast<__half2*>(&r)[1] = __floats2half2_rn(v.z, v.w);
    return r;
}

// ---------------- CSR build ----------------
__global__ void k_count(const int* __restrict__ dst, int e) {
    int i = blockIdx.x * blockDim.x + threadIdx.x;
    if (i < 64) g_pref[i] = -2147483647 - 1;   // sentinel for chained scan
    if (i < e) atomicAdd(&g_deg[dst[i]], 1);
}

// single-kernel chained scan: inclusive block scan + spin-wait on predecessor prefix
__global__ void k_scan(int n) {
    __shared__ int sm[1024];
    __shared__ int s_pre;
    int i = blockIdx.x * 1024 + threadIdx.x;
    int v = (i < n) ? g_deg[i] : 0;
    sm[threadIdx.x] = v;
    __syncthreads();
    for (int s = 1; s < 1024; s <<= 1) {
        int t = (threadIdx.x >= s) ? sm[threadIdx.x - s] : 0;
        __syncthreads();
        sm[threadIdx.x] += t;
        __syncthreads();
    }
    if (threadIdx.x == 1023) {
        int total = sm[1023];
        int pre = 0;
        if (blockIdx.x > 0) {
            volatile int* vp = g_pref;
            int t;
            while ((t = vp[blockIdx.x - 1]) == (-2147483647 - 1)) {}
            pre = t;
        }
        atomicExch(&g_pref[blockIdx.x], pre + total);
        s_pre = pre;
    }
    __syncthreads();
    if (i < n) {
        g_off[i + 1] = sm[threadIdx.x] + s_pre;
        g_dinv[i] = rsqrtf((float)(v + 1));   // +1 self loop
    }
    if (i == 0) g_off[0] = 0;
}

// claims slots by decrementing g_deg -> leaves g_deg zeroed for next replay
__global__ void k_fill(const int* __restrict__ src, const int* __restrict__ dst, int e) {
    int i = blockIdx.x * blockDim.x + threadIdx.x;
    if (i < e) {
        int d = dst[i];
        int p = atomicSub(&g_deg[d], 1);
        g_col[g_off[d] + p - 1] = src[i];
    }
}

// ---------------- tensor-core GEMM: out[M,NC] = A[M,K] @ W[K,NC] ----------------
template <int K, int NC, bool AF16, bool OUTH, bool BIAS, bool RELU>
__global__ void k_mma(const void* __restrict__ Ap, const float* __restrict__ W,
                      const float* __restrict__ bias, void* __restrict__ outp, int M) {
    constexpr int BM = 128, BN = 64, BK = 32, PAD = 8;
    __shared__ __half As[BM][BK + PAD];
    __shared__ __half Bs[BN][BK + PAD];

    const int tid = threadIdx.x;
    const int wid = tid >> 5, lane = tid & 31;
    const int warp_m = wid & 3, warp_n = wid >> 2;
    const int g = lane >> 2, tig = lane & 3;
    const int row0 = blockIdx.x * BM;
    const int col0 = blockIdx.y * BN;

    float acc[2][4][4];
#pragma unroll
    for (int mt = 0; mt < 2; mt++)
#pragma unroll
        for (int nt = 0; nt < 4; nt++)
#pragma unroll
            for (int i = 0; i < 4; i++) acc[mt][nt][i] = 0.f;

    for (int k0 = 0; k0 < K; k0 += BK) {
#pragma unroll
        for (int it = 0; it < 2; it++) {
            int idx = tid + it * 256;
            int r = idx >> 2, ch = idx & 3;
            int gr = row0 + r;
            int4 val;
            if (gr < M) {
                if (AF16) {
                    const int4* A16 = (const int4*)Ap;
                    val = A16[(size_t)gr * (K / 8) + (k0 >> 3) + ch];
                } else {
                    const float* Af = (const float*)Ap;
                    const float4* p = (const float4*)&Af[(size_t)gr * K + k0 + ch * 8];
                    float4 f0 = p[0], f1 = p[1];
                    __half2* h = (__half2*)&val;
                    h[0] = __floats2half2_rn(f0.x, f0.y);
                    h[1] = __floats2half2_rn(f0.z, f0.w);
                    h[2] = __floats2half2_rn(f1.x, f1.y);
                    h[3] = __floats2half2_rn(f1.z, f1.w);
                }
            } else {
                val = make_int4(0, 0, 0, 0);
            }
            *(int4*)&As[r][ch * 8] = val;
        }
#pragma unroll
        for (int i = 0; i < 8; i++) {
            int lin = tid + i * 256;
            int kk = lin >> 6, n = lin & 63;
            Bs[n][kk] = __float2half(W[(size_t)(k0 + kk) * NC + col0 + n]);
        }
        __syncthreads();

#pragma unroll
        for (int ks = 0; ks < BK; ks += 16) {
            u32 a[2][4], b[4][2];
#pragma unroll
            for (int mt = 0; mt < 2; mt++) {
                int rb = warp_m * 32 + mt * 16 + g;
                a[mt][0] = *(const u32*)&As[rb][ks + 2 * tig];
                a[mt][1] = *(const u32*)&As[rb + 8][ks + 2 * tig];
                a[mt][2] = *(const u32*)&As[rb][ks + 2 * tig + 8];
                a[mt][3] = *(const u32*)&As[rb + 8][ks + 2 * tig + 8];
            }
#pragma unroll
            for (int nt = 0; nt < 4; nt++) {
                int nb = warp_n * 32 + nt * 8 + g;
                b[nt][0] = *(const u32*)&Bs[nb][ks + 2 * tig];
                b[nt][1] = *(const u32*)&Bs[nb][ks + 2 * tig + 8];
            }
#pragma unroll
            for (int mt = 0; mt < 2; mt++)
#pragma unroll
                for (int nt = 0; nt < 4; nt++) {
                    asm volatile(
                        "mma.sync.aligned.m16n8k16.row.col.f32.f16.f16.f32 "
                        "{%0,%1,%2,%3}, {%4,%5,%6,%7}, {%8,%9}, {%0,%1,%2,%3};"
                        : "+f"(acc[mt][nt][0]), "+f"(acc[mt][nt][1]),
                          "+f"(acc[mt][nt][2]), "+f"(acc[mt][nt][3])
                        : "r"(a[mt][0]), "r"(a[mt][1]), "r"(a[mt][2]), "r"(a[mt][3]),
                          "r"(b[nt][0]), "r"(b[nt][1]));
                }
        }
        __syncthreads();
    }

    float* outf = (float*)outp;
    __half* outh = (__half*)outp;
#pragma unroll
    for (int mt = 0; mt < 2; mt++) {
        int r0 = row0 + warp_m * 32 + mt * 16 + g;
#pragma unroll
        for (int nt = 0; nt < 4; nt++) {
            int gc = col0 + warp_n * 32 + nt * 8 + 2 * tig;
            float2 v0 = make_float2(acc[mt][nt][0], acc[mt][nt][1]);
            float2 v1 = make_float2(acc[mt][nt][2], acc[mt][nt][3]);
            if (BIAS) {
                float2 bb = *(const float2*)&bias[gc];
                v0.x += bb.x; v0.y += bb.y; v1.x += bb.x; v1.y += bb.y;
            }
            if (RELU) {
                v0.x = fmaxf(v0.x, 0.f); v0.y = fmaxf(v0.y, 0.f);
                v1.x = fmaxf(v1.x, 0.f); v1.y = fmaxf(v1.y, 0.f);
            }
            if (r0 < M) {
                if (OUTH) *(__half2*)&outh[(size_t)r0 * NC + gc] = __floats2half2_rn(v0.x, v0.y);
                else      *(float2*)&outf[(size_t)r0 * NC + gc] = v0;
            }
            if (r0 + 8 < M) {
                if (OUTH) *(__half2*)&outh[(size_t)(r0 + 8) * NC + gc] = __floats2half2_rn(v1.x, v1.y);
                else      *(float2*)&outf[(size_t)(r0 + 8) * NC + gc] = v1;
            }
        }
    }
}

// ---------------- fused mu/logvar/z MMA: one pass over h2 ----------------
__global__ void k_mulvz(const void* __restrict__ Ap,
                        const float* __restrict__ Wm, const float* __restrict__ bm,
                        const float* __restrict__ Wl, const float* __restrict__ bl,
                        const float* __restrict__ eps,
                        float* __restrict__ out_mu, float* __restrict__ out_lv,
                        __half* __restrict__ zbuf, int M) {
    constexpr int K = 64, NC = 64, BM = 128, BK = 32, PAD = 8;
    __shared__ __half As[BM][BK + PAD];
    __shared__ __half Bm[NC][BK + PAD];
    __shared__ __half Bl[NC][BK + PAD];

    const int tid = threadIdx.x;
    const int wid = tid >> 5, lane = tid & 31;
    const int warp_m = wid & 3, warp_n = wid >> 2;
    const int g = lane >> 2, tig = lane & 3;
    const int row0 = blockIdx.x * BM;

    float am[2][4][4], al[2][4][4];
#pragma unroll
    for (int mt = 0; mt < 2; mt++)
#pragma unroll
        for (int nt = 0; nt < 4; nt++)
#pragma unroll
            for (int i = 0; i < 4; i++) { am[mt][nt][i] = 0.f; al[mt][nt][i] = 0.f; }

    for (int k0 = 0; k0 < K; k0 += BK) {
#pragma unroll
        for (int it = 0; it < 2; it++) {
            int idx = tid + it * 256;
            int r = idx >> 2, ch = idx & 3;
            int gr = row0 + r;
            int4 val = make_int4(0, 0, 0, 0);
            if (gr < M) {
                const int4* A16 = (const int4*)Ap;
                val = A16[(size_t)gr * (K / 8) + (k0 >> 3) + ch];
            }
            *(int4*)&As[r][ch * 8] = val;
        }
#pragma unroll
        for (int i = 0; i < 8; i++) {
            int lin = tid + i * 256;
            int kk = lin >> 6, n = lin & 63;
            Bm[n][kk] = __float2half(Wm[(size_t)(k0 + kk) * NC + n]);
            Bl[n][kk] = __float2half(Wl[(size_t)(k0 + kk) * NC + n]);
        }
        __syncthreads();

#pragma unroll
        for (int ks = 0; ks < BK; ks += 16) {
            u32 a[2][4], b[4][2], c[4][2];
#pragma unroll
            for (int mt = 0; mt < 2; mt++) {
                int rb = warp_m * 32 + mt * 16 + g;
                a[mt][0] = *(const u32*)&As[rb][ks + 2 * tig];
                a[mt][1] = *(const u32*)&As[rb + 8][ks + 2 * tig];
                a[mt][2] = *(const u32*)&As[rb][ks + 2 * tig + 8];
                a[mt][3] = *(const u32*)&As[rb + 8][ks + 2 * tig + 8];
            }
#pragma unroll
            for (int nt = 0; nt < 4; nt++) {
                int nb = warp_n * 32 + nt * 8 + g;
                b[nt][0] = *(const u32*)&Bm[nb][ks + 2 * tig];
                b[nt][1] = *(const u32*)&Bm[nb][ks + 2 * tig + 8];
                c[nt][0] = *(const u32*)&Bl[nb][ks + 2 * tig];
                c[nt][1] = *(const u32*)&Bl[nb][ks + 2 * tig + 8];
            }
#pragma unroll
            for (int mt = 0; mt < 2; mt++)
#pragma unroll
                for (int nt = 0; nt < 4; nt++) {
                    asm volatile(
                        "mma.sync.aligned.m16n8k16.row.col.f32.f16.f16.f32 "
                        "{%0,%1,%2,%3}, {%4,%5,%6,%7}, {%8,%9}, {%0,%1,%2,%3};"
                        : "+f"(am[mt][nt][0]), "+f"(am[mt][nt][1]),
                          "+f"(am[mt][nt][2]), "+f"(am[mt][nt][3])
                        : "r"(a[mt][0]), "r"(a[mt][1]), "r"(a[mt][2]), "r"(a[mt][3]),
                          "r"(b[nt][0]), "r"(b[nt][1]));
                    asm volatile(
                        "mma.sync.aligned.m16n8k16.row.col.f32.f16.f16.f32 "
                        "{%0,%1,%2,%3}, {%4,%5,%6,%7}, {%8,%9}, {%0,%1,%2,%3};"
                        : "+f"(al[mt][nt][0]), "+f"(al[mt][nt][1]),
                          "+f"(al[mt][nt][2]), "+f"(al[mt][nt][3])
                        : "r"(a[mt][0]), "r"(a[mt][1]), "r"(a[mt][2]), "r"(a[mt][3]),
                          "r"(c[nt][0]), "r"(c[nt][1]));
                }
        }
        __syncthreads();
    }

#pragma unroll
    for (int mt = 0; mt < 2; mt++) {
        int rbase = row0 + warp_m * 32 + mt * 16 + g;
#pragma unroll
        for (int nt = 0; nt < 4; nt++) {
            int gc = warp_n * 32 + nt * 8 + 2 * tig;
            float2 bmu = *(const float2*)&bm[gc];
            float2 blv = *(const float2*)&bl[gc];
#pragma unroll
            for (int hh = 0; hh < 2; hh++) {
                int r = rbase + hh * 8;
                if (r >= M) continue;
                float2 mu = make_float2(am[mt][nt][2 * hh] + bmu.x,
                                        am[mt][nt][2 * hh + 1] + bmu.y);
                float2 lv = make_float2(al[mt][nt][2 * hh] + blv.x,
                                        al[mt][nt][2 * hh + 1] + blv.y);
                float2 ep = *(const float2*)&eps[(size_t)r * NC + gc];
                float2 z = make_float2(mu.x + ep.x * expf(0.5f * lv.x),
                                       mu.y + ep.y * expf(0.5f * lv.y));
                *(float2*)&out_mu[(size_t)r * NC + gc] = mu;
                *(float2*)&out_lv[(size_t)r * NC + gc] = lv;
                *(__half2*)&zbuf[(size_t)r * NC + gc] = __floats2half2_rn(z.x, z.y);
            }
        }
    }
}

// ---------------- fused decoder: hs2 = relu(t@W_d1 + b_d1) @ W_d2  (fp16 in/out) ----------------
// Dynamic smem: As1[128][72] | Bs[128][72] (stage1 W_d1 / stage2 W_d2 chunks) | P[128][136]
__global__ void k_dec(const int4* __restrict__ tA, const float* __restrict__ Wd1,
                      const float* __restrict__ bd1, const float* __restrict__ Wd2,
                      __half* __restrict__ outp, int M) {
    extern __shared__ __align__(16) char ds[];
    __half (*As1)[72] = reinterpret_cast<__half(*)[72]>(ds);                  // 18432 B
    __half (*Bs)[72]  = reinterpret_cast<__half(*)[72]>(ds + 18432);          // 18432 B
    __half (*P)[136]  = reinterpret_cast<__half(*)[136]>(ds + 2 * 18432);     // 34816 B

    const int tid = threadIdx.x;
    const int wid = tid >> 5, lane = tid & 31;
    const int warp_m = wid & 3, warp_n = wid >> 2;
    const int g = lane >> 2, tig = lane & 3;
    const int row0 = blockIdx.x * 128;

    // ---- load t tile (128 x 64 fp16) ----
#pragma unroll
    for (int it = 0; it < 4; it++) {
        int idx = tid + it * 256;            // 0..1023
        int r = idx >> 3, ch = idx & 7;
        int gr = row0 + r;
        int4 val = make_int4(0, 0, 0, 0);
        if (gr < M) val = tA[(size_t)gr * 8 + ch];
        *(int4*)&As1[r][ch * 8] = val;
    }
    // ---- load W_d1 (64k x 128n) transposed ----
#pragma unroll
    for (int i = 0; i < 32; i++) {
        int lin = tid + i * 256;             // 0..8191
        int kk = lin >> 7, n = lin & 127;
        Bs[n][kk] = __float2half(Wd1[(size_t)kk * 128 + n]);
    }
    __syncthreads();

    // ---- stage 1: P = relu(t @ W_d1 + b_d1), warp tile 32m x 64n ----
    float acc1[2][8][4];
#pragma unroll
    for (int mt = 0; mt < 2; mt++)
#pragma unroll
        for (int nt = 0; nt < 8; nt++)
#pragma unroll
            for (int i = 0; i < 4; i++) acc1[mt][nt][i] = 0.f;

#pragma unroll
    for (int ks = 0; ks < 64; ks += 16) {
        u32 a[2][4], b[8][2];
#pragma unroll
        for (int mt = 0; mt < 2; mt++) {
            int rb = warp_m * 32 + mt * 16 + g;
            a[mt][0] = *(const u32*)&As1[rb][ks + 2 * tig];
            a[mt][1] = *(const u32*)&As1[rb + 8][ks + 2 * tig];
            a[mt][2] = *(const u32*)&As1[rb][ks + 2 * tig + 8];
            a[mt][3] = *(const u32*)&As1[rb + 8][ks + 2 * tig + 8];
        }
#pragma unroll
        for (int nt = 0; nt < 8; nt++) {
            int nb = warp_n * 64 + nt * 8 + g;
            b[nt][0] = *(const u32*)&Bs[nb][ks + 2 * tig];
            b[nt][1] = *(const u32*)&Bs[nb][ks + 2 * tig + 8];
        }
#pragma unroll
        for (int mt = 0; mt < 2; mt++)
#pragma unroll
            for (int nt = 0; nt < 8; nt++) {
                asm volatile(
                    "mma.sync.aligned.m16n8k16.row.col.f32.f16.f16.f32 "
                    "{%0,%1,%2,%3}, {%4,%5,%6,%7}, {%8,%9}, {%0,%1,%2,%3};"
                    : "+f"(acc1[mt][nt][0]), "+f"(acc1[mt][nt][1]),
                      "+f"(acc1[mt][nt][2]), "+f"(acc1[mt][nt][3])
                    : "r"(a[mt][0]), "r"(a[mt][1]), "r"(a[mt][2]), "r"(a[mt][3]),
                      "r"(b[nt][0]), "r"(b[nt][1]));
            }
    }
    __syncthreads();   // As1/Bs reads done before P writes & Bs reuse

    // epilogue 1 -> P (fp16, smem)
#pragma unroll
    for (int mt = 0; mt < 2; mt++) {
        int r0 = warp_m * 32 + mt * 16 + g;
#pragma unroll
        for (int nt = 0; nt < 8; nt++) {
            int gc = warp_n * 64 + nt * 8 + 2 * tig;
            float2 bb = *(const float2*)&bd1[gc];
            float2 v0 = make_float2(fmaxf(acc1[mt][nt][0] + bb.x, 0.f),
                                    fmaxf(acc1[mt][nt][1] + bb.y, 0.f));
            float2 v1 = make_float2(fmaxf(acc1[mt][nt][2] + bb.x, 0.f),
                                    fmaxf(acc1[mt][nt][3] + bb.y, 0.f));
            *(__half2*)&P[r0][gc] = __floats2half2_rn(v0.x, v0.y);
            *(__half2*)&P[r0 + 8][gc] = __floats2half2_rn(v1.x, v1.y);
        }
    }

    // ---- stage 2: hs2 = P @ W_d2 (128k), BK=32 chunks through Bs ----
    float acc2[2][8][4];
#pragma unroll
    for (int mt = 0; mt < 2; mt++)
#pragma unroll
        for (int nt = 0; nt < 8; nt++)
#pragma unroll
            for (int i = 0; i < 4; i++) acc2[mt][nt][i] = 0.f;

    for (int k0 = 0; k0 < 128; k0 += 32) {
        __syncthreads();   // previous Bs use (or P writes) complete
#pragma unroll
        for (int i = 0; i < 16; i++) {
            int lin = tid + i * 256;         // 0..4095
            int kk = lin >> 7, n = lin & 127;
            Bs[n][kk] = __float2half(Wd2[(size_t)(k0 + kk) * 128 + n]);
        }
        __syncthreads();
#pragma unroll
        for (int ks = 0; ks < 32; ks += 16) {
            u32 a[2][4], b[8][2];
#pragma unroll
            for (int mt = 0; mt < 2; mt++) {
                int rb = warp_m * 32 + mt * 16 + g;
                a[mt][0] = *(const u32*)&P[rb][k0 + ks + 2 * tig];
                a[mt][1] = *(const u32*)&P[rb + 8][k0 + ks + 2 * tig];
                a[mt][2] = *(const u32*)&P[rb][k0 + ks + 2 * tig + 8];
                a[mt][3] = *(const u32*)&P[rb + 8][k0 + ks + 2 * tig + 8];
            }
#pragma unroll
            for (int nt = 0; nt < 8; nt++) {
                int nb = warp_n * 64 + nt * 8 + g;
                b[nt][0] = *(const u32*)&Bs[nb][ks + 2 * tig];
                b[nt][1] = *(const u32*)&Bs[nb][ks + 2 * tig + 8];
            }
#pragma unroll
            for (int mt = 0; mt < 2; mt++)
#pragma unroll
                for (int nt = 0; nt < 8; nt++) {
                    asm volatile(
                        "mma.sync.aligned.m16n8k16.row.col.f32.f16.f16.f32 "
                        "{%0,%1,%2,%3}, {%4,%5,%6,%7}, {%8,%9}, {%0,%1,%2,%3};"
                        : "+f"(acc2[mt][nt][0]), "+f"(acc2[mt][nt][1]),
                          "+f"(acc2[mt][nt][2]), "+f"(acc2[mt][nt][3])
                        : "r"(a[mt][0]), "r"(a[mt][1]), "r"(a[mt][2]), "r"(a[mt][3]),
                          "r"(b[nt][0]), "r"(b[nt][1]));
                }
        }
    }

    // epilogue 2 -> gmem fp16
#pragma unroll
    for (int mt = 0; mt < 2; mt++) {
        int r0 = row0 + warp_m * 32 + mt * 16 + g;
#pragma unroll
        for (int nt = 0; nt < 8; nt++) {
            int gc = warp_n * 64 + nt * 8 + 2 * tig;
            if (r0 < M)
                *(__half2*)&outp[(size_t)r0 * 128 + gc] =
                    __floats2half2_rn(acc2[mt][nt][0], acc2[mt][nt][1]);
            if (r0 + 8 < M)
                *(__half2*)&outp[(size_t)(r0 + 8) * 128 + gc] =
                    __floats2half2_rn(acc2[mt][nt][2], acc2[mt][nt][3]);
        }
    }
}

// ---------------- pull aggregation over fp16 features (R4 proven form) ----------------
template <int C, bool BIAS, bool RELU, bool OUTH>
__global__ void k_agg(const u64* __restrict__ hs, const float* __restrict__ bias,
                      void* __restrict__ outp, int n) {
    constexpr int L = C / 4;
    int lane = threadIdx.x;
    int node = blockIdx.x * blockDim.y + threadIdx.y;
    if (node >= n) return;
    float di = g_dinv[node];
    float4 sv = h4f(hs[(size_t)node * L + lane]);
    float4 acc = make_float4(sv.x * di, sv.y * di, sv.z * di, sv.w * di);
    int b0 = g_off[node], b1 = g_off[node + 1];
    int j = b0;
    for (; j + 3 < b1; j += 4) {
        int s0 = g_col[j], s1 = g_col[j + 1], s2 = g_col[j + 2], s3 = g_col[j + 3];
        float d0 = g_dinv[s0], d1 = g_dinv[s1], d2 = g_dinv[s2], d3 = g_dinv[s3];
        float4 v0 = h4f(hs[(size_t)s0 * L + lane]);
        float4 v1 = h4f(hs[(size_t)s1 * L + lane]);
        float4 v2 = h4f(hs[(size_t)s2 * L + lane]);
        float4 v3 = h4f(hs[(size_t)s3 * L + lane]);
        acc.x += v0.x * d0 + v1.x * d1 + v2.x * d2 + v3.x * d3;
        acc.y += v0.y * d0 + v1.y * d1 + v2.y * d2 + v3.y * d3;
        acc.z += v0.z * d0 + v1.z * d1 + v2.z * d2 + v3.z * d3;
        acc.w += v0.w * d0 + v1.w * d1 + v2.w * d2 + v3.w * d3;
    }
    for (; j < b1; j++) {
        int s = g_col[j];
        float ds = g_dinv[s];
        float4 v = h4f(hs[(size_t)s * L + lane]);
        acc.x += v.x * ds; acc.y += v.y * ds; acc.z += v.z * ds; acc.w += v.w * ds;
    }
    float4 o = make_float4(acc.x * di, acc.y * di, acc.z * di, acc.w * di);
    if (BIAS) {
        float4 bb = reinterpret_cast<const float4*>(bias)[lane];
        o.x += bb.x; o.y += bb.y; o.z += bb.z; o.w += bb.w;
    }
    if (RELU) {
        o.x = fmaxf(o.x, 0.f); o.y = fmaxf(o.y, 0.f);
        o.z = fmaxf(o.z, 0.f); o.w = fmaxf(o.w, 0.f);
    }
    if (OUTH) reinterpret_cast<u64*>(outp)[(size_t)node * L + lane] = f4h(o);
    else      reinterpret_cast<float4*>(outp)[(size_t)node * L + lane] = o;
}

extern "C" void kernel_launch(void* const* d_in, const int* in_sizes, int n_in,
                              void* d_out, int out_size) {
    const float* x    = (const float*)d_in[0];
    const int*   ei   = (const int*)d_in[1];
    const float* eps  = (const float*)d_in[2];
    const float* W_e1 = (const float*)d_in[3];
    const float* b_e1 = (const float*)d_in[4];
    const float* W_e2 = (const float*)d_in[5];
    const float* b_e2 = (const float*)d_in[6];
    const float* W_mu = (const float*)d_in[7];
    const float* b_mu = (const float*)d_in[8];
    const float* W_lv = (const float*)d_in[9];
    const float* b_lv = (const float*)d_in[10];
    const float* W_d1 = (const float*)d_in[11];
    const float* b_d1 = (const float*)d_in[12];
    const float* W_d2 = (const float*)d_in[13];
    const float* b_d2 = (const float*)d_in[14];

    int N = in_sizes[0] / INC;
    int E = in_sizes[1] / 2;
    const int* src = ei;
    const int* dst = ei + E;

    float* out    = (float*)d_out;
    float* out_d  = out;
    float* out_mu = out + (size_t)N * 128;
    float* out_lv = out_mu + (size_t)N * 64;

    float* bufA; float* bufB;
    cudaGetSymbolAddress((void**)&bufA, g_bufA);
    cudaGetSymbolAddress((void**)&bufB, g_bufB);
    u64* hA = (u64*)bufA;
    u64* hB = (u64*)bufB;

    static cudaStream_t s2 = nullptr;
    static cudaEvent_t evF = nullptr, evJ = nullptr;
    static bool attrSet = false;
    if (!s2) {
        cudaStreamCreateWithFlags(&s2, cudaStreamNonBlocking);
        cudaEventCreateWithFlags(&evF, cudaEventDisableTiming);
        cudaEventCreateWithFlags(&evJ, cudaEventDisableTiming);
    }
    if (!attrSet) {
        cudaFuncSetAttribute(k_dec, cudaFuncAttributeMaxDynamicSharedMemorySize, 72192);
        attrSet = true;
    }

    int nbScan = (N + 1023) / 1024;
    int mBlk = (N + 127) / 128;

    // ---- CSR build on side stream (overlaps e1 GEMM): 3 launches ----
    cudaEventRecord(evF, 0);
    cudaStreamWaitEvent(s2, evF, 0);
    k_count<<<(E + 255) / 256, 256, 0, s2>>>(dst, E);
    k_scan<<<nbScan, 1024, 0, s2>>>(N);
    k_fill<<<(E + 255) / 256, 256, 0, s2>>>(src, dst, E);
    cudaEventRecord(evJ, s2);

    // ---- encoder conv1 GEMM: hs = x@W_e1 -> fp16 hA ----
    k_mma<128, 128, false, true, false, false><<<dim3(mBlk, 2), 256>>>(
        x, W_e1, nullptr, hA, N);

    cudaStreamWaitEvent(0, evJ, 0);

    // ---- h1 = relu(Â hs + b_e1) -> fp16 hB ----
    k_agg<128, true, true, true><<<(N + 7) / 8, dim3(32, 8)>>>(hA, b_e1, hB, N);

    // ---- encoder conv2: hs = h1@W_e2 -> fp16 hA ; h2 = Â hs + b_e2 -> fp16 hB ----
    k_mma<128, 64, true, true, false, false><<<dim3(mBlk, 1), 256>>>(
        hB, W_e2, nullptr, hA, N);
    k_agg<64, true, false, true><<<(N + 15) / 16, dim3(16, 16)>>>(hA, b_e2, hB, N);

    // ---- fused mu/logvar/z: mu,lv -> out (fp32) ; z -> fp16 hA ----
    k_mulvz<<<mBlk, 256>>>(hB, W_mu, b_mu, W_lv, b_lv, eps,
                           out_mu, out_lv, (__half*)hA, N);

    // ---- decoder: t = Â z -> fp16 hB ; hs2 = relu(t@W_d1+b)@W_d2 -> fp16 hA (fused) ----
    k_agg<64, false, false, true><<<(N + 15) / 16, dim3(16, 16)>>>(hA, nullptr, hB, N);
    k_dec<<<mBlk, 256, 72192>>>((const int4*)hB, W_d1, b_d1, W_d2, (__half*)hA, N);

    // ---- final: d = Â hs2 + b_d2 -> fp32 out ----
    k_agg<128, true, false, false><<<(N + 7) / 8, dim3(32, 8)>>>(hA, b_d2, out_d, N);
}

// round 17
// speedup vs baseline: 1.0755x; 1.0755x over previous
#include <cuda_runtime.h>
#include <cuda_bf16.h>
#include <cuda_fp16.h>
#include <math.h>

#define MAXN 50000
#define MAXE 800000
#define INC 128

typedef unsigned long long u64;
typedef unsigned int u32;

// ---------------- scratch (no allocation allowed) ----------------
__device__ __align__(16) float g_bufA[MAXN * 128];
__device__ __align__(16) float g_bufB[MAXN * 128];
__device__ float g_dinv[MAXN];
__device__ int   g_deg[MAXN];
__device__ int   g_off[MAXN + 1];
__device__ int   g_col[MAXE];
__device__ int   g_blksum[64];

// ---------------- helpers ----------------
__device__ __forceinline__ float4 h4f(u64 v) {
    __half2 a = reinterpret_cast<__half2*>(&v)[0];
    __half2 b = reinterpret_cast<__half2*>(&v)[1];
    float2 fa = __half22float2(a), fb = __half22float2(b);
    return make_float4(fa.x, fa.y, fb.x, fb.y);
}
__device__ __forceinline__ u64 f4h(float4 v) {
    u64 r;
    reinterpret_cast<__half2*>(&r)[0] = __floats2half2_rn(v.x, v.y);
    reinterpret_cast<__half2*>(&r)[1] = __floats2half2_rn(v.z, v.w);
    return r;
}

// ---------------- CSR build (proven 3-kernel scan) ----------------
__global__ void k_count(const int* __restrict__ dst, int e) {
    int i = blockIdx.x * blockDim.x + threadIdx.x;
    if (i < e) atomicAdd(&g_deg[dst[i]], 1);
}

__global__ void k_scanA(int n) {
    __shared__ int sm[1024];
    int i = blockIdx.x * 1024 + threadIdx.x;
    int v = (i < n) ? g_deg[i] : 0;
    sm[threadIdx.x] = v;
    __syncthreads();
    for (int s = 1; s < 1024; s <<= 1) {
        int t = (threadIdx.x >= s) ? sm[threadIdx.x - s] : 0;
        __syncthreads();
        sm[threadIdx.x] += t;
        __syncthreads();
    }
    if (i < n) g_off[i + 1] = sm[threadIdx.x];
    if (threadIdx.x == 1023) g_blksum[blockIdx.x] = sm[1023];
}

__global__ void k_scanB(int nb) {
    __shared__ int sm[64];
    int t = threadIdx.x;
    int v = (t < nb) ? g_blksum[t] : 0;
    sm[t] = v;
    __syncthreads();
    for (int s = 1; s < 64; s <<= 1) {
        int u = (t >= s) ? sm[t - s] : 0;
        __syncthreads();
        sm[t] += u;
        __syncthreads();
    }
    if (t < nb) g_blksum[t] = sm[t] - v;  // exclusive
}

__global__ void k_scanC(int n) {
    int i = blockIdx.x * 1024 + threadIdx.x;
    if (i < n) {
        g_off[i + 1] += g_blksum[blockIdx.x];
        g_dinv[i] = rsqrtf((float)(g_deg[i] + 1));
    }
    if (i == 0) g_off[0] = 0;
}

__global__ void k_fill(const int* __restrict__ src, const int* __restrict__ dst, int e) {
    int i = blockIdx.x * blockDim.x + threadIdx.x;
    if (i < e) {
        int d = dst[i];
        int p = atomicSub(&g_deg[d], 1);
        g_col[g_off[d] + p - 1] = src[i];
    }
}

// ---------------- tensor-core GEMM, high-reuse warp tiles ----------------
// 128 threads, BM=128, BN=NC (grid.y=1). Warps 2(m)x2(n): warp tile 64 x BN/2.
// MACs per smem byte = 16 (BN=128) vs 8 in the 32x32 version -> half the L1 traffic.
template <int K, int NC, bool AF16, bool OUTH, bool BIAS, bool RELU>
__global__ void __launch_bounds__(128, 2) k_mma(
        const void* __restrict__ Ap, const float* __restrict__ W,
        const float* __restrict__ bias, void* __restrict__ outp, int M) {
    constexpr int BM = 128, BN = NC, BK = 32, PAD = 8;
    constexpr int NT = BN / 16;            // n8 tiles per warp (warp spans BN/2)
    __shared__ __half As[BM][BK + PAD];
    __shared__ __half Bs[BN][BK + PAD];

    const int tid = threadIdx.x;
    const int wid = tid >> 5, lane = tid & 31;
    const int warp_m = wid & 1, warp_n = wid >> 1;
    const int g = lane >> 2, tig = lane & 3;
    const int row0 = blockIdx.x * BM;

    float acc[4][NT][4];
#pragma unroll
    for (int mt = 0; mt < 4; mt++)
#pragma unroll
        for (int nt = 0; nt < NT; nt++)
#pragma unroll
            for (int i = 0; i < 4; i++) acc[mt][nt][i] = 0.f;

    for (int k0 = 0; k0 < K; k0 += BK) {
        // ---- A tile: 128 rows x 32 halves (4 int4-chunks/row, 4 iters) ----
#pragma unroll
        for (int it = 0; it < 4; it++) {
            int idx = tid + it * 128;        // 0..511
            int r = idx >> 2, ch = idx & 3;
            int gr = row0 + r;
            int4 val;
            if (gr < M) {
                if (AF16) {
                    const int4* A16 = (const int4*)Ap;
                    val = A16[(size_t)gr * (K / 8) + (k0 >> 3) + ch];
                } else {
                    const float* Af = (const float*)Ap;
                    const float4* p = (const float4*)&Af[(size_t)gr * K + k0 + ch * 8];
                    float4 f0 = p[0], f1 = p[1];
                    __half2* h = (__half2*)&val;
                    h[0] = __floats2half2_rn(f0.x, f0.y);
                    h[1] = __floats2half2_rn(f0.z, f0.w);
                    h[2] = __floats2half2_rn(f1.x, f1.y);
                    h[3] = __floats2half2_rn(f1.z, f1.w);
                }
            } else {
                val = make_int4(0, 0, 0, 0);
            }
            *(int4*)&As[r][ch * 8] = val;
        }
        // ---- B tile: W[k0..+31][0..BN) -> Bs[n][k] ----
#pragma unroll
        for (int i = 0; i < BN * BK / 128; i++) {
            int lin = tid + i * 128;
            int kk = lin / BN, n = lin % BN;
            Bs[n][kk] = __float2half(W[(size_t)(k0 + kk) * NC + n]);
        }
        __syncthreads();

#pragma unroll
        for (int ks = 0; ks < BK; ks += 16) {
            u32 a[4][4], b[NT][2];
#pragma unroll
            for (int mt = 0; mt < 4; mt++) {
                int rb = warp_m * 64 + mt * 16 + g;
                a[mt][0] = *(const u32*)&As[rb][ks + 2 * tig];
                a[mt][1] = *(const u32*)&As[rb + 8][ks + 2 * tig];
                a[mt][2] = *(const u32*)&As[rb][ks + 2 * tig + 8];
                a[mt][3] = *(const u32*)&As[rb + 8][ks + 2 * tig + 8];
            }
#pragma unroll
            for (int nt = 0; nt < NT; nt++) {
                int nb = warp_n * (BN / 2) + nt * 8 + g;
                b[nt][0] = *(const u32*)&Bs[nb][ks + 2 * tig];
                b[nt][1] = *(const u32*)&Bs[nb][ks + 2 * tig + 8];
            }
#pragma unroll
            for (int mt = 0; mt < 4; mt++)
#pragma unroll
                for (int nt = 0; nt < NT; nt++) {
                    asm volatile(
                        "mma.sync.aligned.m16n8k16.row.col.f32.f16.f16.f32 "
                        "{%0,%1,%2,%3}, {%4,%5,%6,%7}, {%8,%9}, {%0,%1,%2,%3};"
                        : "+f"(acc[mt][nt][0]), "+f"(acc[mt][nt][1]),
                          "+f"(acc[mt][nt][2]), "+f"(acc[mt][nt][3])
                        : "r"(a[mt][0]), "r"(a[mt][1]), "r"(a[mt][2]), "r"(a[mt][3]),
                          "r"(b[nt][0]), "r"(b[nt][1]));
                }
        }
        __syncthreads();
    }

    float* outf = (float*)outp;
    __half* outh = (__half*)outp;
#pragma unroll
    for (int mt = 0; mt < 4; mt++) {
        int r0 = row0 + warp_m * 64 + mt * 16 + g;
#pragma unroll
        for (int nt = 0; nt < NT; nt++) {
            int gc = warp_n * (BN / 2) + nt * 8 + 2 * tig;
            float2 v0 = make_float2(acc[mt][nt][0], acc[mt][nt][1]);
            float2 v1 = make_float2(acc[mt][nt][2], acc[mt][nt][3]);
            if (BIAS) {
                float2 bb = *(const float2*)&bias[gc];
                v0.x += bb.x; v0.y += bb.y; v1.x += bb.x; v1.y += bb.y;
            }
            if (RELU) {
                v0.x = fmaxf(v0.x, 0.f); v0.y = fmaxf(v0.y, 0.f);
                v1.x = fmaxf(v1.x, 0.f); v1.y = fmaxf(v1.y, 0.f);
            }
            if (r0 < M) {
                if (OUTH) *(__half2*)&outh[(size_t)r0 * NC + gc] = __floats2half2_rn(v0.x, v0.y);
                else      *(float2*)&outf[(size_t)r0 * NC + gc] = v0;
            }
            if (r0 + 8 < M) {
                if (OUTH) *(__half2*)&outh[(size_t)(r0 + 8) * NC + gc] = __floats2half2_rn(v1.x, v1.y);
                else      *(float2*)&outf[(size_t)(r0 + 8) * NC + gc] = v1;
            }
        }
    }
}

// ---------------- fused mu/logvar/z MMA (unchanged) ----------------
__global__ void k_mulvz(const void* __restrict__ Ap,
                        const float* __restrict__ Wm, const float* __restrict__ bm,
                        const float* __restrict__ Wl, const float* __restrict__ bl,
                        const float* __restrict__ eps,
                        float* __restrict__ out_mu, float* __restrict__ out_lv,
                        __half* __restrict__ zbuf, int M) {
    constexpr int K = 64, NC = 64, BM = 128, BK = 32, PAD = 8;
    __shared__ __half As[BM][BK + PAD];
    __shared__ __half Bm[NC][BK + PAD];
    __shared__ __half Bl[NC][BK + PAD];

    const int tid = threadIdx.x;
    const int wid = tid >> 5, lane = tid & 31;
    const int warp_m = wid & 3, warp_n = wid >> 2;
    const int g = lane >> 2, tig = lane & 3;
    const int row0 = blockIdx.x * BM;

    float am[2][4][4], al[2][4][4];
#pragma unroll
    for (int mt = 0; mt < 2; mt++)
#pragma unroll
        for (int nt = 0; nt < 4; nt++)
#pragma unroll
            for (int i = 0; i < 4; i++) { am[mt][nt][i] = 0.f; al[mt][nt][i] = 0.f; }

    for (int k0 = 0; k0 < K; k0 += BK) {
#pragma unroll
        for (int it = 0; it < 2; it++) {
            int idx = tid + it * 256;
            int r = idx >> 2, ch = idx & 3;
            int gr = row0 + r;
            int4 val = make_int4(0, 0, 0, 0);
            if (gr < M) {
                const int4* A16 = (const int4*)Ap;
                val = A16[(size_t)gr * (K / 8) + (k0 >> 3) + ch];
            }
            *(int4*)&As[r][ch * 8] = val;
        }
#pragma unroll
        for (int i = 0; i < 8; i++) {
            int lin = tid + i * 256;
            int kk = lin >> 6, n = lin & 63;
            Bm[n][kk] = __float2half(Wm[(size_t)(k0 + kk) * NC + n]);
            Bl[n][kk] = __float2half(Wl[(size_t)(k0 + kk) * NC + n]);
        }
        __syncthreads();

#pragma unroll
        for (int ks = 0; ks < BK; ks += 16) {
            u32 a[2][4], b[4][2], c[4][2];
#pragma unroll
            for (int mt = 0; mt < 2; mt++) {
                int rb = warp_m * 32 + mt * 16 + g;
                a[mt][0] = *(const u32*)&As[rb][ks + 2 * tig];
                a[mt][1] = *(const u32*)&As[rb + 8][ks + 2 * tig];
                a[mt][2] = *(const u32*)&As[rb][ks + 2 * tig + 8];
                a[mt][3] = *(const u32*)&As[rb + 8][ks + 2 * tig + 8];
            }
#pragma unroll
            for (int nt = 0; nt < 4; nt++) {
                int nb = warp_n * 32 + nt * 8 + g;
                b[nt][0] = *(const u32*)&Bm[nb][ks + 2 * tig];
                b[nt][1] = *(const u32*)&Bm[nb][ks + 2 * tig + 8];
                c[nt][0] = *(const u32*)&Bl[nb][ks + 2 * tig];
                c[nt][1] = *(const u32*)&Bl[nb][ks + 2 * tig + 8];
            }
#pragma unroll
            for (int mt = 0; mt < 2; mt++)
#pragma unroll
                for (int nt = 0; nt < 4; nt++) {
                    asm volatile(
                        "mma.sync.aligned.m16n8k16.row.col.f32.f16.f16.f32 "
                        "{%0,%1,%2,%3}, {%4,%5,%6,%7}, {%8,%9}, {%0,%1,%2,%3};"
                        : "+f"(am[mt][nt][0]), "+f"(am[mt][nt][1]),
                          "+f"(am[mt][nt][2]), "+f"(am[mt][nt][3])
                        : "r"(a[mt][0]), "r"(a[mt][1]), "r"(a[mt][2]), "r"(a[mt][3]),
                          "r"(b[nt][0]), "r"(b[nt][1]));
                    asm volatile(
                        "mma.sync.aligned.m16n8k16.row.col.f32.f16.f16.f32 "
                        "{%0,%1,%2,%3}, {%4,%5,%6,%7}, {%8,%9}, {%0,%1,%2,%3};"
                        : "+f"(al[mt][nt][0]), "+f"(al[mt][nt][1]),
                          "+f"(al[mt][nt][2]), "+f"(al[mt][nt][3])
                        : "r"(a[mt][0]), "r"(a[mt][1]), "r"(a[mt][2]), "r"(a[mt][3]),
                          "r"(c[nt][0]), "r"(c[nt][1]));
                }
        }
        __syncthreads();
    }

#pragma unroll
    for (int mt = 0; mt < 2; mt++) {
        int rbase = row0 + warp_m * 32 + mt * 16 + g;
#pragma unroll
        for (int nt = 0; nt < 4; nt++) {
            int gc = warp_n * 32 + nt * 8 + 2 * tig;
            float2 bmu = *(const float2*)&bm[gc];
            float2 blv = *(const float2*)&bl[gc];
#pragma unroll
            for (int hh = 0; hh < 2; hh++) {
                int r = rbase + hh * 8;
                if (r >= M) continue;
                float2 mu = make_float2(am[mt][nt][2 * hh] + bmu.x,
                                        am[mt][nt][2 * hh + 1] + bmu.y);
                float2 lv = make_float2(al[mt][nt][2 * hh] + blv.x,
                                        al[mt][nt][2 * hh + 1] + blv.y);
                float2 ep = *(const float2*)&eps[(size_t)r * NC + gc];
                float2 z = make_float2(mu.x + ep.x * expf(0.5f * lv.x),
                                       mu.y + ep.y * expf(0.5f * lv.y));
                *(float2*)&out_mu[(size_t)r * NC + gc] = mu;
                *(float2*)&out_lv[(size_t)r * NC + gc] = lv;
                *(__half2*)&zbuf[(size_t)r * NC + gc] = __floats2half2_rn(z.x, z.y);
            }
        }
    }
}

// ---------------- pull aggregation over fp16 features (R4 proven form) ----------------
template <int C, bool BIAS, bool RELU, bool OUTH>
__global__ void k_agg(const u64* __restrict__ hs, const float* __restrict__ bias,
                      void* __restrict__ outp, int n) {
    constexpr int L = C / 4;
    int lane = threadIdx.x;
    int node = blockIdx.x * blockDim.y + threadIdx.y;
    if (node >= n) return;
    float di = g_dinv[node];
    float4 sv = h4f(hs[(size_t)node * L + lane]);
    float4 acc = make_float4(sv.x * di, sv.y * di, sv.z * di, sv.w * di);
    int b0 = g_off[node], b1 = g_off[node + 1];
    int j = b0;
    for (; j + 3 < b1; j += 4) {
        int s0 = g_col[j], s1 = g_col[j + 1], s2 = g_col[j + 2], s3 = g_col[j + 3];
        float d0 = g_dinv[s0], d1 = g_dinv[s1], d2 = g_dinv[s2], d3 = g_dinv[s3];
        float4 v0 = h4f(hs[(size_t)s0 * L + lane]);
        float4 v1 = h4f(hs[(size_t)s1 * L + lane]);
        float4 v2 = h4f(hs[(size_t)s2 * L + lane]);
        float4 v3 = h4f(hs[(size_t)s3 * L + lane]);
        acc.x += v0.x * d0 + v1.x * d1 + v2.x * d2 + v3.x * d3;
        acc.y += v0.y * d0 + v1.y * d1 + v2.y * d2 + v3.y * d3;
        acc.z += v0.z * d0 + v1.z * d1 + v2.z * d2 + v3.z * d3;
        acc.w += v0.w * d0 + v1.w * d1 + v2.w * d2 + v3.w * d3;
    }
    for (; j < b1; j++) {
        int s = g_col[j];
        float ds = g_dinv[s];
        float4 v = h4f(hs[(size_t)s * L + lane]);
        acc.x += v.x * ds; acc.y += v.y * ds; acc.z += v.z * ds; acc.w += v.w * ds;
    }
    float4 o = make_float4(acc.x * di, acc.y * di, acc.z * di, acc.w * di);
    if (BIAS) {
        float4 bb = reinterpret_cast<const float4*>(bias)[lane];
        o.x += bb.x; o.y += bb.y; o.z += bb.z; o.w += bb.w;
    }
    if (RELU) {
        o.x = fmaxf(o.x, 0.f); o.y = fmaxf(o.y, 0.f);
        o.z = fmaxf(o.z, 0.f); o.w = fmaxf(o.w, 0.f);
    }
    if (OUTH) reinterpret_cast<u64*>(outp)[(size_t)node * L + lane] = f4h(o);
    else      reinterpret_cast<float4*>(outp)[(size_t)node * L + lane] = o;
}

extern "C" void kernel_launch(void* const* d_in, const int* in_sizes, int n_in,
                              void* d_out, int out_size) {
    const float* x    = (const float*)d_in[0];
    const int*   ei   = (const int*)d_in[1];
    const float* eps  = (const float*)d_in[2];
    const float* W_e1 = (const float*)d_in[3];
    const float* b_e1 = (const float*)d_in[4];
    const float* W_e2 = (const float*)d_in[5];
    const float* b_e2 = (const float*)d_in[6];
    const float* W_mu = (const float*)d_in[7];
    const float* b_mu = (const float*)d_in[8];
    const float* W_lv = (const float*)d_in[9];
    const float* b_lv = (const float*)d_in[10];
    const float* W_d1 = (const float*)d_in[11];
    const float* b_d1 = (const float*)d_in[12];
    const float* W_d2 = (const float*)d_in[13];
    const float* b_d2 = (const float*)d_in[14];

    int N = in_sizes[0] / INC;
    int E = in_sizes[1] / 2;
    const int* src = ei;
    const int* dst = ei + E;

    float* out    = (float*)d_out;
    float* out_d  = out;
    float* out_mu = out + (size_t)N * 128;
    float* out_lv = out_mu + (size_t)N * 64;

    float* bufA; float* bufB;
    cudaGetSymbolAddress((void**)&bufA, g_bufA);
    cudaGetSymbolAddress((void**)&bufB, g_bufB);
    u64* hA = (u64*)bufA;
    u64* hB = (u64*)bufB;

    static cudaStream_t s2 = nullptr;
    static cudaEvent_t evF = nullptr, evJ = nullptr;
    if (!s2) {
        cudaStreamCreateWithFlags(&s2, cudaStreamNonBlocking);
        cudaEventCreateWithFlags(&evF, cudaEventDisableTiming);
        cudaEventCreateWithFlags(&evJ, cudaEventDisableTiming);
    }

    int nbScan = (N + 1023) / 1024;
    int mBlk = (N + 127) / 128;

    // ---- CSR build on side stream (overlaps e1 GEMM) ----
    cudaEventRecord(evF, 0);
    cudaStreamWaitEvent(s2, evF, 0);
    k_count<<<(E + 255) / 256, 256, 0, s2>>>(dst, E);
    k_scanA<<<nbScan, 1024, 0, s2>>>(N);
    k_scanB<<<1, 64, 0, s2>>>(nbScan);
    k_scanC<<<nbScan, 1024, 0, s2>>>(N);
    k_fill<<<(E + 255) / 256, 256, 0, s2>>>(src, dst, E);
    cudaEventRecord(evJ, s2);

    // ---- encoder conv1 GEMM: hs = x@W_e1 -> fp16 hA ----
    k_mma<128, 128, false, true, false, false><<<mBlk, 128>>>(x, W_e1, nullptr, hA, N);

    cudaStreamWaitEvent(0, evJ, 0);

    // ---- h1 = relu(Â hs + b_e1) -> fp16 hB ----
    k_agg<128, true, true, true><<<(N + 7) / 8, dim3(32, 8)>>>(hA, b_e1, hB, N);

    // ---- encoder conv2: hs = h1@W_e2 -> fp16 hA ; h2 = Â hs + b_e2 -> fp16 hB ----
    k_mma<128, 64, true, true, false, false><<<mBlk, 128>>>(hB, W_e2, nullptr, hA, N);
    k_agg<64, true, false, true><<<(N + 15) / 16, dim3(16, 16)>>>(hA, b_e2, hB, N);

    // ---- fused mu/logvar/z: mu,lv -> out (fp32) ; z -> fp16 hA ----
    k_mulvz<<<mBlk, 256>>>(hB, W_mu, b_mu, W_lv, b_lv, eps,
                           out_mu, out_lv, (__half*)hA, N);

    // ---- decoder conv1 (reordered): t = Â z -> fp16 hB ; d1 = relu(t@W_d1+b) -> fp16 hA ----
    k_agg<64, false, false, true><<<(N + 15) / 16, dim3(16, 16)>>>(hA, nullptr, hB, N);
    k_mma<64, 128, true, true, true, true><<<mBlk, 128>>>(hB, W_d1, b_d1, hA, N);

    // ---- decoder conv2: hs = d1@W_d2 -> fp16 hB ; d = Â hs + b_d2 -> fp32 out ----
    k_mma<128, 128, true, true, false, false><<<mBlk, 128>>>(hA, W_d2, nullptr, hB, N);
    k_agg<128, true, false, false><<<(N + 7) / 8, dim3(32, 8)>>>(hB, b_d2, out_d, N);
}